// round 1
// baseline (speedup 1.0000x reference)
#include <cuda_runtime.h>

// Problem constants (CausalSelfAttention: B=2, T=2048, C=1024, H=16, D=64)
#define BB   2
#define TT   2048
#define CC   1024
#define NH   16
#define HD   64
#define MROWS (BB*TT)          // 4096

// Scratch (no cudaMalloc allowed): qkv [B*T, 3C] and attention output [B*T, C]
__device__ float g_qkv[(size_t)MROWS * 3 * CC];   // 50.3 MB
__device__ float g_att[(size_t)MROWS * CC];       // 16.8 MB

// ---------------------------------------------------------------------------
// SGEMM: C[M,N] = A[M,K] @ B[K,N] + bias[N]
// 128x128 tile, BK=16, 256 threads, 8x8 register microtile.
// Assumes M%128==0, N%128==0, K%16==0 (true for all shapes here).
// ---------------------------------------------------------------------------
__global__ __launch_bounds__(256) void sgemm_bias(
    const float* __restrict__ A, const float* __restrict__ Bm,
    const float* __restrict__ bias, float* __restrict__ Cm,
    int M, int N, int K)
{
    __shared__ float As[16 * 136];   // A tile transposed [k][row], padded stride 136
    __shared__ float Bs[16 * 128];   // B tile [k][col]

    const int tid = threadIdx.x;
    const int tx = tid & 15;         // col group
    const int ty = tid >> 4;         // row group
    const int brow = blockIdx.y * 128;
    const int bcol = blockIdx.x * 128;

    float acc[8][8];
    #pragma unroll
    for (int i = 0; i < 8; ++i)
        #pragma unroll
        for (int j = 0; j < 8; ++j) acc[i][j] = 0.f;

    const int nk = K >> 4;
    for (int kt = 0; kt < nk; ++kt) {
        // --- load A tile: 128 rows x 16 k, store transposed ---
        #pragma unroll
        for (int i = 0; i < 2; ++i) {
            int idx = tid + i * 256;           // 512 float4 total
            int row = idx >> 2;
            int c4  = idx & 3;
            float4 v = *(const float4*)(A + (size_t)(brow + row) * K + kt * 16 + c4 * 4);
            As[(c4 * 4 + 0) * 136 + row] = v.x;
            As[(c4 * 4 + 1) * 136 + row] = v.y;
            As[(c4 * 4 + 2) * 136 + row] = v.z;
            As[(c4 * 4 + 3) * 136 + row] = v.w;
        }
        // --- load B tile: 16 k x 128 cols ---
        #pragma unroll
        for (int i = 0; i < 2; ++i) {
            int idx = tid + i * 256;
            int row = idx >> 5;
            int c4  = idx & 31;
            *(float4*)(Bs + row * 128 + c4 * 4) =
                *(const float4*)(Bm + (size_t)(kt * 16 + row) * N + bcol + c4 * 4);
        }
        __syncthreads();

        #pragma unroll
        for (int kk = 0; kk < 16; ++kk) {
            const float4* Ar = (const float4*)(As + kk * 136);
            const float4* Br = (const float4*)(Bs + kk * 128);
            float4 a0 = Ar[ty * 2], a1 = Ar[ty * 2 + 1];
            float4 b0 = Br[tx * 2], b1 = Br[tx * 2 + 1];
            float a[8] = {a0.x, a0.y, a0.z, a0.w, a1.x, a1.y, a1.z, a1.w};
            float b[8] = {b0.x, b0.y, b0.z, b0.w, b1.x, b1.y, b1.z, b1.w};
            #pragma unroll
            for (int i = 0; i < 8; ++i)
                #pragma unroll
                for (int j = 0; j < 8; ++j)
                    acc[i][j] += a[i] * b[j];
        }
        __syncthreads();
    }

    // epilogue: + bias, vectorized store
    float4 bia0 = *(const float4*)(bias + bcol + tx * 8);
    float4 bia1 = *(const float4*)(bias + bcol + tx * 8 + 4);
    #pragma unroll
    for (int i = 0; i < 8; ++i) {
        int row = brow + ty * 8 + i;
        float* dst = Cm + (size_t)row * N + bcol + tx * 8;
        float4 o0 = make_float4(acc[i][0] + bia0.x, acc[i][1] + bia0.y,
                                acc[i][2] + bia0.z, acc[i][3] + bia0.w);
        float4 o1 = make_float4(acc[i][4] + bia1.x, acc[i][5] + bia1.y,
                                acc[i][6] + bia1.z, acc[i][7] + bia1.w);
        *(float4*)(dst)     = o0;
        *(float4*)(dst + 4) = o1;
    }
}

// ---------------------------------------------------------------------------
// Fused causal attention over the packed qkv buffer.
// One thread per query row; 128 query rows per CTA; K/V tiles (64 keys) in smem.
// Online softmax (flash style), fp32 throughout.
// Output written in [B, T, H, D] = [B*T, C] layout for the out-projection GEMM.
// ---------------------------------------------------------------------------
__global__ __launch_bounds__(128) void attn_kernel(
    const float* __restrict__ qkv, float* __restrict__ out)
{
    __shared__ float Ks[64 * 64];
    __shared__ float Vs[64 * 64];

    const int tid = threadIdx.x;
    const int h = blockIdx.y;
    const int b = blockIdx.z;
    const int q0 = blockIdx.x * 128;
    const int qrow = q0 + tid;
    const float scale = 0.125f;    // 1/sqrt(64)

    // Q row -> registers, pre-scaled
    const float* qptr = qkv + (size_t)(b * TT + qrow) * (3 * CC) + h * HD;
    float4 q[16];
    #pragma unroll
    for (int i = 0; i < 16; ++i) {
        q[i] = ((const float4*)qptr)[i];
        q[i].x *= scale; q[i].y *= scale; q[i].z *= scale; q[i].w *= scale;
    }

    float4 o[16];
    #pragma unroll
    for (int i = 0; i < 16; ++i) o[i] = make_float4(0.f, 0.f, 0.f, 0.f);
    float m = -1e30f;
    float l = 0.f;

    const int ntiles = (q0 >> 6) + 2;   // key tiles [0, q0+128)
    for (int kt = 0; kt < ntiles; ++kt) {
        const int k0 = kt * 64;
        // cooperative K/V tile load (64 keys x 64 dims each)
        const float* kbase = qkv + (size_t)(b * TT + k0) * (3 * CC) + CC + h * HD;
        const float* vbase = kbase + CC;
        #pragma unroll
        for (int i = 0; i < 8; ++i) {
            int idx = i * 128 + tid;       // 1024 float4
            int key = idx >> 4;
            int d4  = idx & 15;
            ((float4*)Ks)[key * 16 + d4] = *(const float4*)(kbase + (size_t)key * (3 * CC) + d4 * 4);
            ((float4*)Vs)[key * 16 + d4] = *(const float4*)(vbase + (size_t)key * (3 * CC) + d4 * 4);
        }
        __syncthreads();

        const int jmax = qrow - k0;                 // causal: valid j <= jmax
        const int jend = (jmax >= 63) ? 64 : (jmax + 1);
        for (int j = 0; j < jend; ++j) {
            const float4* kr = (const float4*)(Ks + j * 64);
            float s = 0.f;
            #pragma unroll
            for (int i = 0; i < 16; ++i) {
                float4 kv = kr[i];
                s += q[i].x * kv.x + q[i].y * kv.y + q[i].z * kv.z + q[i].w * kv.w;
            }
            const float4* vr = (const float4*)(Vs + j * 64);
            if (s <= m) {
                float p = __expf(s - m);
                l += p;
                #pragma unroll
                for (int i = 0; i < 16; ++i) {
                    float4 vv = vr[i];
                    o[i].x += p * vv.x; o[i].y += p * vv.y;
                    o[i].z += p * vv.z; o[i].w += p * vv.w;
                }
            } else {
                float corr = __expf(m - s);
                m = s;
                l = l * corr + 1.f;
                #pragma unroll
                for (int i = 0; i < 16; ++i) {
                    float4 vv = vr[i];
                    o[i].x = o[i].x * corr + vv.x; o[i].y = o[i].y * corr + vv.y;
                    o[i].z = o[i].z * corr + vv.z; o[i].w = o[i].w * corr + vv.w;
                }
            }
        }
        __syncthreads();
    }

    const float inv = 1.f / l;
    float* optr = out + (size_t)(b * TT + qrow) * CC + h * HD;
    #pragma unroll
    for (int i = 0; i < 16; ++i) {
        float4 v = o[i];
        v.x *= inv; v.y *= inv; v.z *= inv; v.w *= inv;
        ((float4*)optr)[i] = v;
    }
}

// ---------------------------------------------------------------------------
extern "C" void kernel_launch(void* const* d_in, const int* in_sizes, int n_in,
                              void* d_out, int out_size)
{
    (void)in_sizes; (void)n_in; (void)out_size;
    const float* x     = (const float*)d_in[0];   // [B,T,C]
    const float* w_qkv = (const float*)d_in[1];   // [C,3C]
    const float* b_qkv = (const float*)d_in[2];   // [3C]
    const float* w_out = (const float*)d_in[3];   // [C,C]
    const float* b_out = (const float*)d_in[4];   // [C]
    float* out = (float*)d_out;                   // [B,T,C]

    float* qkv = nullptr;
    float* att = nullptr;
    cudaGetSymbolAddress((void**)&qkv, g_qkv);
    cudaGetSymbolAddress((void**)&att, g_att);

    // 1) qkv = x @ w_qkv + b_qkv      (M=4096, N=3072, K=1024)
    {
        dim3 grid(3 * CC / 128, MROWS / 128);
        sgemm_bias<<<grid, 256>>>(x, w_qkv, b_qkv, qkv, MROWS, 3 * CC, CC);
    }
    // 2) fused causal attention -> att in [B*T, C] layout
    {
        dim3 grid(TT / 128, NH, BB);
        attn_kernel<<<grid, 128>>>(qkv, att);
    }
    // 3) out = att @ w_out + b_out    (M=4096, N=1024, K=1024)
    {
        dim3 grid(CC / 128, MROWS / 128);
        sgemm_bias<<<grid, 256>>>(att, w_out, b_out, out, MROWS, CC, CC);
    }
}

// round 3
// speedup vs baseline: 3.7115x; 3.7115x over previous
#include <cuda_runtime.h>
#include <cstdint>

// Problem constants: B=2, T=2048, C=1024, H=16, D=64
#define BB   2
#define TT   2048
#define CC   1024
#define NH   16
#define HD   64
#define MROWS (BB*TT)          // 4096

// Scratch buffers (no cudaMalloc allowed)
__device__ float g_qkv[(size_t)MROWS * 3 * CC];   // [B*T, 3C]
__device__ float g_att[(size_t)MROWS * CC];       // [B*T, C]

// ---------------------------------------------------------------------------
// helpers
// ---------------------------------------------------------------------------
// tf32 conversion: destination must be a b32 register per PTX ISA.
__device__ __forceinline__ unsigned f2tf32u(float x) {
    unsigned r; asm("cvt.rna.tf32.f32 %0, %1;" : "=r"(r) : "f"(x)); return r;
}
__device__ __forceinline__ float f2tf32f(float x) {
    return __uint_as_float(f2tf32u(x));
}
__device__ __forceinline__ unsigned fasu(float x) { return __float_as_uint(x); }

// D += A(16x8) @ B(8x8), tf32 operands, fp32 accum
__device__ __forceinline__ void mma8(float4& d,
    unsigned a0, unsigned a1, unsigned a2, unsigned a3,
    unsigned b0, unsigned b1)
{
    asm volatile(
        "mma.sync.aligned.m16n8k8.row.col.f32.tf32.tf32.f32 "
        "{%0,%1,%2,%3}, {%4,%5,%6,%7}, {%8,%9}, {%0,%1,%2,%3};\n"
        : "+f"(d.x), "+f"(d.y), "+f"(d.z), "+f"(d.w)
        : "r"(a0), "r"(a1), "r"(a2), "r"(a3), "r"(b0), "r"(b1));
}

// ---------------------------------------------------------------------------
// tf32 tensor-core GEMM: C[M,N] = A[M,K] @ B[K,N] + bias[N]
// 128x128 tile, BK=16, 256 threads (8 warps, 2x4), warp tile 64x32.
// Double-buffered smem; pad 136 -> conflict-free fragment LDS.
// ---------------------------------------------------------------------------
__global__ __launch_bounds__(256) void gemm_tf32(
    const float* __restrict__ A, const float* __restrict__ B,
    const float* __restrict__ bias, float* __restrict__ C,
    int M, int N, int K)
{
    __shared__ float As[2][16][136];   // [k][row], transposed A tile (tf32 values)
    __shared__ float Bs[2][16][136];   // [k][col]

    const int tid  = threadIdx.x;
    const int lane = tid & 31, warp = tid >> 5;
    const int wm = warp & 1;           // 0..1 -> 64 rows each
    const int wn = warp >> 1;          // 0..3 -> 32 cols each
    const int qp = lane & 3, qr = lane >> 2;
    const int brow = blockIdx.y * 128;
    const int bcol = blockIdx.x * 128;

    float4 acc[4][4];
    #pragma unroll
    for (int i = 0; i < 4; ++i)
        #pragma unroll
        for (int j = 0; j < 4; ++j) acc[i][j] = make_float4(0.f, 0.f, 0.f, 0.f);

    const int nk = K >> 4;
    float4 ra[2], rb[2];

    // ---- prologue: load + store tile 0 ----
    #pragma unroll
    for (int i = 0; i < 2; ++i) {
        int row = (tid >> 2) + i * 64;
        ra[i] = *(const float4*)(A + (size_t)(brow + row) * K + (tid & 3) * 4);
        int idx = tid + i * 256, brw = idx >> 5, c4 = idx & 31;
        rb[i] = *(const float4*)(B + (size_t)brw * N + bcol + c4 * 4);
    }
    #pragma unroll
    for (int i = 0; i < 2; ++i) {
        int row = (tid >> 2) + i * 64, c0 = (tid & 3) * 4;
        As[0][c0+0][row] = f2tf32f(ra[i].x); As[0][c0+1][row] = f2tf32f(ra[i].y);
        As[0][c0+2][row] = f2tf32f(ra[i].z); As[0][c0+3][row] = f2tf32f(ra[i].w);
        int idx = tid + i * 256, brw = idx >> 5, c4 = idx & 31;
        *(float4*)&Bs[0][brw][c4*4] = make_float4(f2tf32f(rb[i].x), f2tf32f(rb[i].y),
                                                  f2tf32f(rb[i].z), f2tf32f(rb[i].w));
    }

    for (int kt = 0; kt < nk; ++kt) {
        __syncthreads();
        const int cur = kt & 1;
        const bool more = (kt + 1 < nk);
        if (more) {
            #pragma unroll
            for (int i = 0; i < 2; ++i) {
                int row = (tid >> 2) + i * 64;
                ra[i] = *(const float4*)(A + (size_t)(brow + row) * K + (kt+1)*16 + (tid & 3) * 4);
                int idx = tid + i * 256, brw = idx >> 5, c4 = idx & 31;
                rb[i] = *(const float4*)(B + (size_t)((kt+1)*16 + brw) * N + bcol + c4 * 4);
            }
        }
        #pragma unroll
        for (int ks = 0; ks < 2; ++ks) {
            const int k0 = ks * 8 + qp;
            unsigned af[4][4], bf[4][2];
            #pragma unroll
            for (int mt = 0; mt < 4; ++mt) {
                int r = wm * 64 + mt * 16 + qr;
                af[mt][0] = fasu(As[cur][k0  ][r]);   af[mt][1] = fasu(As[cur][k0  ][r+8]);
                af[mt][2] = fasu(As[cur][k0+4][r]);   af[mt][3] = fasu(As[cur][k0+4][r+8]);
            }
            #pragma unroll
            for (int nt = 0; nt < 4; ++nt) {
                int c = wn * 32 + nt * 8 + qr;
                bf[nt][0] = fasu(Bs[cur][k0][c]); bf[nt][1] = fasu(Bs[cur][k0+4][c]);
            }
            #pragma unroll
            for (int mt = 0; mt < 4; ++mt)
                #pragma unroll
                for (int nt = 0; nt < 4; ++nt)
                    mma8(acc[mt][nt], af[mt][0], af[mt][1], af[mt][2], af[mt][3],
                         bf[nt][0], bf[nt][1]);
        }
        if (more) {
            const int nxt = cur ^ 1;
            #pragma unroll
            for (int i = 0; i < 2; ++i) {
                int row = (tid >> 2) + i * 64, c0 = (tid & 3) * 4;
                As[nxt][c0+0][row] = f2tf32f(ra[i].x); As[nxt][c0+1][row] = f2tf32f(ra[i].y);
                As[nxt][c0+2][row] = f2tf32f(ra[i].z); As[nxt][c0+3][row] = f2tf32f(ra[i].w);
                int idx = tid + i * 256, brw = idx >> 5, c4 = idx & 31;
                *(float4*)&Bs[nxt][brw][c4*4] = make_float4(f2tf32f(rb[i].x), f2tf32f(rb[i].y),
                                                            f2tf32f(rb[i].z), f2tf32f(rb[i].w));
            }
        }
    }

    // ---- epilogue ----
    #pragma unroll
    for (int mt = 0; mt < 4; ++mt) {
        int r0 = brow + wm * 64 + mt * 16 + qr;
        #pragma unroll
        for (int nt = 0; nt < 4; ++nt) {
            int c = bcol + wn * 32 + nt * 8 + 2 * qp;
            float bx = bias[c], by = bias[c+1];
            *(float2*)(C + (size_t)r0      * N + c) = make_float2(acc[mt][nt].x + bx, acc[mt][nt].y + by);
            *(float2*)(C + (size_t)(r0+8)  * N + c) = make_float2(acc[mt][nt].z + bx, acc[mt][nt].w + by);
        }
    }
}

// ---------------------------------------------------------------------------
// Flash attention, tf32 mma. CTA: 64 q-rows (4 warps x 16), k-tiles of 64.
// Ks pad 68 (conflict-free for S b-frags), Vs pad 72 (conflict-free for PV).
// ---------------------------------------------------------------------------
__global__ __launch_bounds__(128) void attn_tf32(
    const float* __restrict__ qkv, float* __restrict__ out)
{
    __shared__ float Ks[64][68];
    __shared__ float Vs[64][72];

    const int tid  = threadIdx.x;
    const int lane = tid & 31, w = tid >> 5;
    const int h = blockIdx.y, b = blockIdx.z;
    const int q0 = blockIdx.x * 64;
    const int qp = lane & 3;      // quad position (col group)
    const int qr = lane >> 2;     // row within quad-group (0..7)
    const unsigned FULL = 0xffffffffu;
    const float scale = 0.125f;   // 1/sqrt(64)

    // ---- Q fragments (pre-scaled, tf32) ----
    unsigned qa[8][4];
    {
        const float* Qg = qkv + (size_t)(b*TT + q0 + w*16) * (3*CC) + h*HD;
        #pragma unroll
        for (int ks = 0; ks < 8; ++ks) {
            int c0 = ks * 8 + qp;
            qa[ks][0] = f2tf32u(Qg[(size_t)qr     * (3*CC) + c0    ] * scale);
            qa[ks][1] = f2tf32u(Qg[(size_t)(qr+8) * (3*CC) + c0    ] * scale);
            qa[ks][2] = f2tf32u(Qg[(size_t)qr     * (3*CC) + c0 + 4] * scale);
            qa[ks][3] = f2tf32u(Qg[(size_t)(qr+8) * (3*CC) + c0 + 4] * scale);
        }
    }

    float4 o[8];
    #pragma unroll
    for (int i = 0; i < 8; ++i) o[i] = make_float4(0.f, 0.f, 0.f, 0.f);
    float m0 = -1e30f, m1 = -1e30f, l0 = 0.f, l1 = 0.f;

    const int ndiag = q0 >> 6;
    for (int kt = 0; kt <= ndiag; ++kt) {
        __syncthreads();
        // ---- cooperative K/V tile load (tf32) ----
        {
            const float* kb = qkv + (size_t)(b*TT + kt*64) * (3*CC) + CC + h*HD;
            const float* vb = kb + CC;
            #pragma unroll
            for (int i = 0; i < 8; ++i) {
                int idx = i * 128 + tid;
                int key = idx >> 4, d4 = (idx & 15) * 4;
                float4 kv = *(const float4*)(kb + (size_t)key * (3*CC) + d4);
                float4 vv = *(const float4*)(vb + (size_t)key * (3*CC) + d4);
                *(float4*)&Ks[key][d4] = make_float4(f2tf32f(kv.x), f2tf32f(kv.y),
                                                     f2tf32f(kv.z), f2tf32f(kv.w));
                *(float4*)&Vs[key][d4] = make_float4(f2tf32f(vv.x), f2tf32f(vv.y),
                                                     f2tf32f(vv.z), f2tf32f(vv.w));
            }
        }
        __syncthreads();

        // ---- S = Q @ K^T  (per warp: 16 x 64) ----
        float4 s[8];
        #pragma unroll
        for (int nt = 0; nt < 8; ++nt) s[nt] = make_float4(0.f, 0.f, 0.f, 0.f);
        #pragma unroll
        for (int nt = 0; nt < 8; ++nt) {
            const int key = nt * 8 + qr;
            #pragma unroll
            for (int ks = 0; ks < 8; ++ks) {
                const int d = ks * 8 + qp;
                unsigned b0 = fasu(Ks[key][d]);
                unsigned b1 = fasu(Ks[key][d + 4]);
                mma8(s[nt], qa[ks][0], qa[ks][1], qa[ks][2], qa[ks][3], b0, b1);
            }
        }

        // ---- causal mask (diagonal tile only) ----
        if (kt == ndiag) {
            const int rg0 = q0 + w * 16 + qr;
            const int rg1 = rg0 + 8;
            #pragma unroll
            for (int nt = 0; nt < 8; ++nt) {
                int cg = kt * 64 + nt * 8 + 2 * qp;
                if (cg     > rg0) s[nt].x = -1e30f;
                if (cg + 1 > rg0) s[nt].y = -1e30f;
                if (cg     > rg1) s[nt].z = -1e30f;
                if (cg + 1 > rg1) s[nt].w = -1e30f;
            }
        }

        // ---- online softmax ----
        float mx0 = -1e30f, mx1 = -1e30f;
        #pragma unroll
        for (int nt = 0; nt < 8; ++nt) {
            mx0 = fmaxf(mx0, fmaxf(s[nt].x, s[nt].y));
            mx1 = fmaxf(mx1, fmaxf(s[nt].z, s[nt].w));
        }
        mx0 = fmaxf(mx0, __shfl_xor_sync(FULL, mx0, 1));
        mx0 = fmaxf(mx0, __shfl_xor_sync(FULL, mx0, 2));
        mx1 = fmaxf(mx1, __shfl_xor_sync(FULL, mx1, 1));
        mx1 = fmaxf(mx1, __shfl_xor_sync(FULL, mx1, 2));

        float nm0 = fmaxf(m0, mx0), nm1 = fmaxf(m1, mx1);
        float al0 = __expf(m0 - nm0), al1 = __expf(m1 - nm1);
        m0 = nm0; m1 = nm1;

        float sum0 = 0.f, sum1 = 0.f;
        #pragma unroll
        for (int nt = 0; nt < 8; ++nt) {
            s[nt].x = __expf(s[nt].x - m0);
            s[nt].y = __expf(s[nt].y - m0);
            s[nt].z = __expf(s[nt].z - m1);
            s[nt].w = __expf(s[nt].w - m1);
            sum0 += s[nt].x + s[nt].y;
            sum1 += s[nt].z + s[nt].w;
        }
        sum0 += __shfl_xor_sync(FULL, sum0, 1);
        sum0 += __shfl_xor_sync(FULL, sum0, 2);
        sum1 += __shfl_xor_sync(FULL, sum1, 1);
        sum1 += __shfl_xor_sync(FULL, sum1, 2);
        l0 = l0 * al0 + sum0;
        l1 = l1 * al1 + sum1;
        #pragma unroll
        for (int nt = 0; nt < 8; ++nt) {
            o[nt].x *= al0; o[nt].y *= al0; o[nt].z *= al1; o[nt].w *= al1;
        }

        // ---- O += P @ V  (A-frags of P built via intra-quad shuffles) ----
        #pragma unroll
        for (int ks = 0; ks < 8; ++ks) {
            const int src  = (lane & ~3) | (qp >> 1);
            const int src2 = src + 2;
            float fx = __shfl_sync(FULL, s[ks].x, src);
            float fy = __shfl_sync(FULL, s[ks].y, src);
            float fz = __shfl_sync(FULL, s[ks].z, src);
            float fw = __shfl_sync(FULL, s[ks].w, src);
            float gx = __shfl_sync(FULL, s[ks].x, src2);
            float gy = __shfl_sync(FULL, s[ks].y, src2);
            float gz = __shfl_sync(FULL, s[ks].z, src2);
            float gw = __shfl_sync(FULL, s[ks].w, src2);
            const bool odd = qp & 1;
            unsigned a0 = f2tf32u(odd ? fy : fx);   // P(r0, 8ks+qp)
            unsigned a1 = f2tf32u(odd ? fw : fz);   // P(r1, 8ks+qp)
            unsigned a2 = f2tf32u(odd ? gy : gx);   // P(r0, 8ks+qp+4)
            unsigned a3 = f2tf32u(odd ? gw : gz);   // P(r1, 8ks+qp+4)
            const int keyb = ks * 8 + qp;
            #pragma unroll
            for (int nt = 0; nt < 8; ++nt) {
                unsigned b0 = fasu(Vs[keyb    ][nt * 8 + qr]);
                unsigned b1 = fasu(Vs[keyb + 4][nt * 8 + qr]);
                mma8(o[nt], a0, a1, a2, a3, b0, b1);
            }
        }
    }

    // ---- writeout: out[b*T + row][h*64 + d] ----
    const float inv0 = 1.f / l0, inv1 = 1.f / l1;
    const int rg0 = b * TT + q0 + w * 16 + qr;
    float* ob = out + (size_t)rg0 * CC + h * HD;
    #pragma unroll
    for (int nt = 0; nt < 8; ++nt) {
        int c = nt * 8 + 2 * qp;
        *(float2*)(ob + c)                   = make_float2(o[nt].x * inv0, o[nt].y * inv0);
        *(float2*)(ob + (size_t)8 * CC + c)  = make_float2(o[nt].z * inv1, o[nt].w * inv1);
    }
}

// ---------------------------------------------------------------------------
extern "C" void kernel_launch(void* const* d_in, const int* in_sizes, int n_in,
                              void* d_out, int out_size)
{
    (void)in_sizes; (void)n_in; (void)out_size;
    const float* x     = (const float*)d_in[0];
    const float* w_qkv = (const float*)d_in[1];
    const float* b_qkv = (const float*)d_in[2];
    const float* w_out = (const float*)d_in[3];
    const float* b_out = (const float*)d_in[4];
    float* out = (float*)d_out;

    float* qkv = nullptr;
    float* att = nullptr;
    cudaGetSymbolAddress((void**)&qkv, g_qkv);
    cudaGetSymbolAddress((void**)&att, g_att);

    // 1) qkv = x @ w_qkv + b_qkv   (M=4096, N=3072, K=1024)
    {
        dim3 grid(3 * CC / 128, MROWS / 128);
        gemm_tf32<<<grid, 256>>>(x, w_qkv, b_qkv, qkv, MROWS, 3 * CC, CC);
    }
    // 2) fused causal attention -> att [B*T, C]
    {
        dim3 grid(TT / 64, NH, BB);
        attn_tf32<<<grid, 128>>>(qkv, att);
    }
    // 3) out = att @ w_out + b_out (M=4096, N=1024, K=1024)
    {
        dim3 grid(CC / 128, MROWS / 128);
        gemm_tf32<<<grid, 256>>>(att, w_out, b_out, out, MROWS, CC, CC);
    }
}

// round 4
// speedup vs baseline: 4.0186x; 1.0827x over previous
#include <cuda_runtime.h>
#include <cstdint>

// Problem constants: B=2, T=2048, C=1024, H=16, D=64
#define BB   2
#define TT   2048
#define CC   1024
#define NH   16
#define HD   64
#define MROWS (BB*TT)          // 4096

// Scratch buffers (no cudaMalloc allowed)
__device__ float g_qkv[(size_t)MROWS * 3 * CC];   // [B*T, 3C]
__device__ float g_att[(size_t)MROWS * CC];       // [B*T, C]

// ---------------------------------------------------------------------------
// helpers
// ---------------------------------------------------------------------------
__device__ __forceinline__ unsigned f2tf32u(float x) {
    unsigned r; asm("cvt.rna.tf32.f32 %0, %1;" : "=r"(r) : "f"(x)); return r;
}
__device__ __forceinline__ float f2tf32f(float x) {
    return __uint_as_float(f2tf32u(x));
}
__device__ __forceinline__ unsigned fasu(float x) { return __float_as_uint(x); }

// D += A(16x8) @ B(8x8), tf32 operands, fp32 accum
__device__ __forceinline__ void mma8(float4& d,
    unsigned a0, unsigned a1, unsigned a2, unsigned a3,
    unsigned b0, unsigned b1)
{
    asm volatile(
        "mma.sync.aligned.m16n8k8.row.col.f32.tf32.tf32.f32 "
        "{%0,%1,%2,%3}, {%4,%5,%6,%7}, {%8,%9}, {%0,%1,%2,%3};\n"
        : "+f"(d.x), "+f"(d.y), "+f"(d.z), "+f"(d.w)
        : "r"(a0), "r"(a1), "r"(a2), "r"(a3), "r"(b0), "r"(b1));
}

// ---------------------------------------------------------------------------
// tf32 tensor-core GEMM: C[M,N] = A[M,K] @ B[K,N] + bias[N]
// 128x128 CTA tile, BK=16, 128 threads (4 warps 2x2), warp tile 64x64.
// Fragment-major smem: A-frag = one LDS.128, B-frag = one LDS.64.
// Pad-33 groups + XOR swizzles -> conflict-free stores AND loads.
//
// A layout: element A[row][k] (row 0..127, k 0..15):
//   g=row>>4, qr=row&7, b1=(row>>3)&1, ks=k>>3, qp=k&3, b2=(k>>2)&1
//   unit16B = (g*2+ks)*33 + ((qr*4+qp) ^ ((qr>>1)&3))
//   floatpos = unit*4 + ((b1+2*b2)^ks)
// B layout: element B[k][col] (k 0..15, col 0..127):
//   gnt=col>>3, qr=col&7, ks=k>>3, qp=k&3, j=(k>>2)&1
//   unit8B = (gnt*2+ks)*33 + ((qr*4+qp) ^ ((qr>>2)&1))
//   floatpos = unit*2 + (j ^ (gnt>>3))
// ---------------------------------------------------------------------------
__global__ __launch_bounds__(128, 2) void gemm_tf32(
    const float* __restrict__ A, const float* __restrict__ B,
    const float* __restrict__ bias, float* __restrict__ C,
    int M, int N, int K)
{
    __shared__ float4 As4[2][528];    // 16 groups * 33 units, x2 buffers
    __shared__ float2 Bs2[2][1056];   // 32 groups * 33 units, x2 buffers

    const int tid  = threadIdx.x;
    const int lane = tid & 31, warp = tid >> 5;
    const int wm = warp & 1;           // row half (64 rows)
    const int wn = warp >> 1;          // col half (64 cols)
    const int qp = lane & 3, qr = lane >> 2;
    const int laneA = (qr * 4 + qp) ^ ((qr >> 1) & 3);
    const int laneB = (qr * 4 + qp) ^ ((qr >> 2) & 1);
    const int brow = blockIdx.y * 128;
    const int bcol = blockIdx.x * 128;

    float4 acc[4][8];
    #pragma unroll
    for (int i = 0; i < 4; ++i)
        #pragma unroll
        for (int j = 0; j < 8; ++j) acc[i][j] = make_float4(0.f, 0.f, 0.f, 0.f);

    const int nk = K >> 4;
    float4 ra[4], rb[4];

    // ---- global tile load into regs for k-tile kt ----
    auto load_tile = [&](int kt) {
        #pragma unroll
        for (int i = 0; i < 4; ++i) {
            int idx = tid + i * 128;
            int arow = idx >> 2, ac0 = (idx & 3) * 4;
            ra[i] = *(const float4*)(A + (size_t)(brow + arow) * K + kt * 16 + ac0);
            int bk = idx >> 5, bc4 = idx & 31;
            rb[i] = *(const float4*)(B + (size_t)(kt * 16 + bk) * N + bcol + bc4 * 4);
        }
    };

    // ---- store staged regs into smem buffer (fragment-major, tf32) ----
    auto store_tile = [&](int buf) {
        float* Asf = (float*)&As4[buf][0];
        float* Bsf = (float*)&Bs2[buf][0];
        #pragma unroll
        for (int i = 0; i < 4; ++i) {
            int idx = tid + i * 128;
            // A
            {
                int arow = idx >> 2, ac0 = (idx & 3) * 4;
                int g = arow >> 4, qrs = arow & 7, b1 = (arow >> 3) & 1;
                int ks = ac0 >> 3, b2 = (ac0 >> 2) & 1;
                int grp = (g * 2 + ks) * 33;
                int off = (b1 + 2 * b2) ^ ks;
                int sx = (qrs >> 1) & 3;
                float v[4] = {ra[i].x, ra[i].y, ra[i].z, ra[i].w};
                #pragma unroll
                for (int q = 0; q < 4; ++q)
                    Asf[(grp + ((qrs * 4 + q) ^ sx)) * 4 + off] = f2tf32f(v[q]);
            }
            // B
            {
                int bk = idx >> 5, bc4 = idx & 31;
                int ks = bk >> 3, qpb = bk & 3, jb = (bk >> 2) & 1;
                int gnt = bc4 >> 1, qrb0 = (bc4 & 1) * 4;
                int xr = bc4 & 1;
                int off = jb ^ (gnt >> 3);
                int grp = (gnt * 2 + ks) * 33;
                float v[4] = {rb[i].x, rb[i].y, rb[i].z, rb[i].w};
                #pragma unroll
                for (int m = 0; m < 4; ++m) {
                    int qrb = qrb0 + m;
                    Bsf[(grp + ((qrb * 4 + qpb) ^ xr)) * 2 + off] = f2tf32f(v[m]);
                }
            }
        }
    };

    // ---- compute one buffered k-tile ----
    auto compute_tile = [&](int buf) {
        #pragma unroll
        for (int ks = 0; ks < 2; ++ks) {
            unsigned af[4][4];
            #pragma unroll
            for (int mt = 0; mt < 4; ++mt) {
                float4 v = As4[buf][((wm * 4 + mt) * 2 + ks) * 33 + laneA];
                if (ks == 0) {
                    af[mt][0] = fasu(v.x); af[mt][1] = fasu(v.y);
                    af[mt][2] = fasu(v.z); af[mt][3] = fasu(v.w);
                } else {
                    af[mt][0] = fasu(v.y); af[mt][1] = fasu(v.x);
                    af[mt][2] = fasu(v.w); af[mt][3] = fasu(v.z);
                }
            }
            unsigned bf[8][2];
            #pragma unroll
            for (int nt = 0; nt < 8; ++nt) {
                float2 v = Bs2[buf][((wn * 8 + nt) * 2 + ks) * 33 + laneB];
                bf[nt][0] = fasu(wn ? v.y : v.x);
                bf[nt][1] = fasu(wn ? v.x : v.y);
            }
            #pragma unroll
            for (int mt = 0; mt < 4; ++mt)
                #pragma unroll
                for (int nt = 0; nt < 8; ++nt)
                    mma8(acc[mt][nt], af[mt][0], af[mt][1], af[mt][2], af[mt][3],
                         bf[nt][0], bf[nt][1]);
        }
    };

    // ---- pipelined main loop ----
    load_tile(0);
    store_tile(0);
    for (int kt = 0; kt < nk; ++kt) {
        __syncthreads();
        const int cur = kt & 1;
        const bool more = (kt + 1 < nk);
        if (more) load_tile(kt + 1);
        compute_tile(cur);
        if (more) store_tile(cur ^ 1);
    }

    // ---- epilogue ----
    #pragma unroll
    for (int mt = 0; mt < 4; ++mt) {
        int r0 = brow + wm * 64 + mt * 16 + qr;
        #pragma unroll
        for (int nt = 0; nt < 8; ++nt) {
            int c = bcol + wn * 64 + nt * 8 + 2 * qp;
            float bx = bias[c], by = bias[c + 1];
            *(float2*)(C + (size_t)r0       * N + c) = make_float2(acc[mt][nt].x + bx, acc[mt][nt].y + by);
            *(float2*)(C + (size_t)(r0 + 8) * N + c) = make_float2(acc[mt][nt].z + bx, acc[mt][nt].w + by);
        }
    }
}

// ---------------------------------------------------------------------------
// Flash attention, tf32 mma. CTA: 64 q-rows (4 warps x 16), k-tiles of 64.
// (unchanged from R3 passing version)
// ---------------------------------------------------------------------------
__global__ __launch_bounds__(128) void attn_tf32(
    const float* __restrict__ qkv, float* __restrict__ out)
{
    __shared__ float Ks[64][68];
    __shared__ float Vs[64][72];

    const int tid  = threadIdx.x;
    const int lane = tid & 31, w = tid >> 5;
    const int h = blockIdx.y, b = blockIdx.z;
    const int q0 = blockIdx.x * 64;
    const int qp = lane & 3;
    const int qr = lane >> 2;
    const unsigned FULL = 0xffffffffu;
    const float scale = 0.125f;

    unsigned qa[8][4];
    {
        const float* Qg = qkv + (size_t)(b*TT + q0 + w*16) * (3*CC) + h*HD;
        #pragma unroll
        for (int ks = 0; ks < 8; ++ks) {
            int c0 = ks * 8 + qp;
            qa[ks][0] = f2tf32u(Qg[(size_t)qr     * (3*CC) + c0    ] * scale);
            qa[ks][1] = f2tf32u(Qg[(size_t)(qr+8) * (3*CC) + c0    ] * scale);
            qa[ks][2] = f2tf32u(Qg[(size_t)qr     * (3*CC) + c0 + 4] * scale);
            qa[ks][3] = f2tf32u(Qg[(size_t)(qr+8) * (3*CC) + c0 + 4] * scale);
        }
    }

    float4 o[8];
    #pragma unroll
    for (int i = 0; i < 8; ++i) o[i] = make_float4(0.f, 0.f, 0.f, 0.f);
    float m0 = -1e30f, m1 = -1e30f, l0 = 0.f, l1 = 0.f;

    const int ndiag = q0 >> 6;
    for (int kt = 0; kt <= ndiag; ++kt) {
        __syncthreads();
        {
            const float* kb = qkv + (size_t)(b*TT + kt*64) * (3*CC) + CC + h*HD;
            const float* vb = kb + CC;
            #pragma unroll
            for (int i = 0; i < 8; ++i) {
                int idx = i * 128 + tid;
                int key = idx >> 4, d4 = (idx & 15) * 4;
                float4 kv = *(const float4*)(kb + (size_t)key * (3*CC) + d4);
                float4 vv = *(const float4*)(vb + (size_t)key * (3*CC) + d4);
                *(float4*)&Ks[key][d4] = make_float4(f2tf32f(kv.x), f2tf32f(kv.y),
                                                     f2tf32f(kv.z), f2tf32f(kv.w));
                *(float4*)&Vs[key][d4] = make_float4(f2tf32f(vv.x), f2tf32f(vv.y),
                                                     f2tf32f(vv.z), f2tf32f(vv.w));
            }
        }
        __syncthreads();

        float4 s[8];
        #pragma unroll
        for (int nt = 0; nt < 8; ++nt) s[nt] = make_float4(0.f, 0.f, 0.f, 0.f);
        #pragma unroll
        for (int nt = 0; nt < 8; ++nt) {
            const int key = nt * 8 + qr;
            #pragma unroll
            for (int ks = 0; ks < 8; ++ks) {
                const int d = ks * 8 + qp;
                unsigned b0 = fasu(Ks[key][d]);
                unsigned b1 = fasu(Ks[key][d + 4]);
                mma8(s[nt], qa[ks][0], qa[ks][1], qa[ks][2], qa[ks][3], b0, b1);
            }
        }

        if (kt == ndiag) {
            const int rg0 = q0 + w * 16 + qr;
            const int rg1 = rg0 + 8;
            #pragma unroll
            for (int nt = 0; nt < 8; ++nt) {
                int cg = kt * 64 + nt * 8 + 2 * qp;
                if (cg     > rg0) s[nt].x = -1e30f;
                if (cg + 1 > rg0) s[nt].y = -1e30f;
                if (cg     > rg1) s[nt].z = -1e30f;
                if (cg + 1 > rg1) s[nt].w = -1e30f;
            }
        }

        float mx0 = -1e30f, mx1 = -1e30f;
        #pragma unroll
        for (int nt = 0; nt < 8; ++nt) {
            mx0 = fmaxf(mx0, fmaxf(s[nt].x, s[nt].y));
            mx1 = fmaxf(mx1, fmaxf(s[nt].z, s[nt].w));
        }
        mx0 = fmaxf(mx0, __shfl_xor_sync(FULL, mx0, 1));
        mx0 = fmaxf(mx0, __shfl_xor_sync(FULL, mx0, 2));
        mx1 = fmaxf(mx1, __shfl_xor_sync(FULL, mx1, 1));
        mx1 = fmaxf(mx1, __shfl_xor_sync(FULL, mx1, 2));

        float nm0 = fmaxf(m0, mx0), nm1 = fmaxf(m1, mx1);
        float al0 = __expf(m0 - nm0), al1 = __expf(m1 - nm1);
        m0 = nm0; m1 = nm1;

        float sum0 = 0.f, sum1 = 0.f;
        #pragma unroll
        for (int nt = 0; nt < 8; ++nt) {
            s[nt].x = __expf(s[nt].x - m0);
            s[nt].y = __expf(s[nt].y - m0);
            s[nt].z = __expf(s[nt].z - m1);
            s[nt].w = __expf(s[nt].w - m1);
            sum0 += s[nt].x + s[nt].y;
            sum1 += s[nt].z + s[nt].w;
        }
        sum0 += __shfl_xor_sync(FULL, sum0, 1);
        sum0 += __shfl_xor_sync(FULL, sum0, 2);
        sum1 += __shfl_xor_sync(FULL, sum1, 1);
        sum1 += __shfl_xor_sync(FULL, sum1, 2);
        l0 = l0 * al0 + sum0;
        l1 = l1 * al1 + sum1;
        #pragma unroll
        for (int nt = 0; nt < 8; ++nt) {
            o[nt].x *= al0; o[nt].y *= al0; o[nt].z *= al1; o[nt].w *= al1;
        }

        #pragma unroll
        for (int ks = 0; ks < 8; ++ks) {
            const int src  = (lane & ~3) | (qp >> 1);
            const int src2 = src + 2;
            float fx = __shfl_sync(FULL, s[ks].x, src);
            float fy = __shfl_sync(FULL, s[ks].y, src);
            float fz = __shfl_sync(FULL, s[ks].z, src);
            float fw = __shfl_sync(FULL, s[ks].w, src);
            float gx = __shfl_sync(FULL, s[ks].x, src2);
            float gy = __shfl_sync(FULL, s[ks].y, src2);
            float gz = __shfl_sync(FULL, s[ks].z, src2);
            float gw = __shfl_sync(FULL, s[ks].w, src2);
            const bool odd = qp & 1;
            unsigned a0 = f2tf32u(odd ? fy : fx);
            unsigned a1 = f2tf32u(odd ? fw : fz);
            unsigned a2 = f2tf32u(odd ? gy : gx);
            unsigned a3 = f2tf32u(odd ? gw : gz);
            const int keyb = ks * 8 + qp;
            #pragma unroll
            for (int nt = 0; nt < 8; ++nt) {
                unsigned b0 = fasu(Vs[keyb    ][nt * 8 + qr]);
                unsigned b1 = fasu(Vs[keyb + 4][nt * 8 + qr]);
                mma8(o[nt], a0, a1, a2, a3, b0, b1);
            }
        }
    }

    const float inv0 = 1.f / l0, inv1 = 1.f / l1;
    const int rg0 = b * TT + q0 + w * 16 + qr;
    float* ob = out + (size_t)rg0 * CC + h * HD;
    #pragma unroll
    for (int nt = 0; nt < 8; ++nt) {
        int c = nt * 8 + 2 * qp;
        *(float2*)(ob + c)                   = make_float2(o[nt].x * inv0, o[nt].y * inv0);
        *(float2*)(ob + (size_t)8 * CC + c)  = make_float2(o[nt].z * inv1, o[nt].w * inv1);
    }
}

// ---------------------------------------------------------------------------
extern "C" void kernel_launch(void* const* d_in, const int* in_sizes, int n_in,
                              void* d_out, int out_size)
{
    (void)in_sizes; (void)n_in; (void)out_size;
    const float* x     = (const float*)d_in[0];
    const float* w_qkv = (const float*)d_in[1];
    const float* b_qkv = (const float*)d_in[2];
    const float* w_out = (const float*)d_in[3];
    const float* b_out = (const float*)d_in[4];
    float* out = (float*)d_out;

    float* qkv = nullptr;
    float* att = nullptr;
    cudaGetSymbolAddress((void**)&qkv, g_qkv);
    cudaGetSymbolAddress((void**)&att, g_att);

    // 1) qkv = x @ w_qkv + b_qkv   (M=4096, N=3072, K=1024)
    {
        dim3 grid(3 * CC / 128, MROWS / 128);
        gemm_tf32<<<grid, 128>>>(x, w_qkv, b_qkv, qkv, MROWS, 3 * CC, CC);
    }
    // 2) fused causal attention -> att [B*T, C]
    {
        dim3 grid(TT / 64, NH, BB);
        attn_tf32<<<grid, 128>>>(qkv, att);
    }
    // 3) out = att @ w_out + b_out (M=4096, N=1024, K=1024)
    {
        dim3 grid(CC / 128, MROWS / 128);
        gemm_tf32<<<grid, 128>>>(att, w_out, b_out, out, MROWS, CC, CC);
    }
}